// round 1
// baseline (speedup 1.0000x reference)
#include <cuda_runtime.h>

#define BB 2
#define TT 2048
#define DD 512
#define HH 8
#define DH 64
#define NINNER 512
#define MAXLAG 5
#define BT (BB*TT)

// Scratch (device globals; no allocation allowed)
__device__ float g_q[BB*HH*TT*DH];
__device__ float g_k[BB*HH*TT*DH];
__device__ float g_v[BB*HH*TT*DH];
__device__ float g_att[BT*NINNER];
__device__ float g_lagp[HH*(MAXLAG+1)];

// ---------------------------------------------------------------------------
// Kernel 0: softmax of lag_weights -> g_lagp  (8 heads x 6 lags)
// ---------------------------------------------------------------------------
__global__ void lag_softmax_kernel(const float* __restrict__ lw) {
    int h = threadIdx.x;
    if (h < HH) {
        float vals[MAXLAG+1];
        float m = -1e30f;
        #pragma unroll
        for (int i = 0; i <= MAXLAG; i++) { vals[i] = lw[h*(MAXLAG+1)+i]; m = fmaxf(m, vals[i]); }
        float s = 0.f;
        #pragma unroll
        for (int i = 0; i <= MAXLAG; i++) { vals[i] = __expf(vals[i]-m); s += vals[i]; }
        #pragma unroll
        for (int i = 0; i <= MAXLAG; i++) g_lagp[h*(MAXLAG+1)+i] = vals[i]/s;
    }
}

// ---------------------------------------------------------------------------
// Kernel 1: QKV GEMM.  y = x @ W  (4096x512 @ 512x512), written as [b,h,t,d].
// 64x64 tile, 256 threads, 4x4 microtile. grid.z selects Wq/Wk/Wv.
// ---------------------------------------------------------------------------
__global__ __launch_bounds__(256) void gemm_qkv_kernel(
    const float* __restrict__ x,
    const float* __restrict__ Wq, const float* __restrict__ Wk,
    const float* __restrict__ Wv)
{
    const float* W = (blockIdx.z == 0) ? Wq : ((blockIdx.z == 1) ? Wk : Wv);
    float* out = (blockIdx.z == 0) ? g_q : ((blockIdx.z == 1) ? g_k : g_v);

    __shared__ float As[16][64];   // A^T tile: As[k][row]
    __shared__ float Bs[16][64];   // W tile:   Bs[k][col]

    int tid = threadIdx.x;
    int tx = tid & 15, ty = tid >> 4;
    int row0 = blockIdx.y * 64, col0 = blockIdx.x * 64;

    float acc[4][4];
    #pragma unroll
    for (int i = 0; i < 4; i++)
        #pragma unroll
        for (int j = 0; j < 4; j++) acc[i][j] = 0.f;

    for (int k0 = 0; k0 < DD; k0 += 16) {
        // Load A tile (64 rows x 16 k) transposed into As[k][row]
        {
            int r  = tid >> 2;          // 0..63
            int c4 = (tid & 3) << 2;    // 0,4,8,12
            float4 av = *(const float4*)(x + (size_t)(row0 + r)*DD + k0 + c4);
            As[c4+0][r] = av.x; As[c4+1][r] = av.y;
            As[c4+2][r] = av.z; As[c4+3][r] = av.w;
            int wr = tid >> 4;          // 0..15
            int wc = (tid & 15) << 2;   // 0..60
            *(float4*)&Bs[wr][wc] = *(const float4*)(W + (size_t)(k0+wr)*NINNER + col0 + wc);
        }
        __syncthreads();
        #pragma unroll
        for (int kk = 0; kk < 16; kk++) {
            float4 a = *(const float4*)&As[kk][ty<<2];
            float4 b = *(const float4*)&Bs[kk][tx<<2];
            acc[0][0] += a.x*b.x; acc[0][1] += a.x*b.y; acc[0][2] += a.x*b.z; acc[0][3] += a.x*b.w;
            acc[1][0] += a.y*b.x; acc[1][1] += a.y*b.y; acc[1][2] += a.y*b.z; acc[1][3] += a.y*b.w;
            acc[2][0] += a.z*b.x; acc[2][1] += a.z*b.y; acc[2][2] += a.z*b.z; acc[2][3] += a.z*b.w;
            acc[3][0] += a.w*b.x; acc[3][1] += a.w*b.y; acc[3][2] += a.w*b.z; acc[3][3] += a.w*b.w;
        }
        __syncthreads();
    }

    // Write into [b,h,t,d]; a 64-wide col block is exactly one head (h = blockIdx.x)
    int h = blockIdx.x;
    #pragma unroll
    for (int i = 0; i < 4; i++) {
        int row = row0 + (ty<<2) + i;          // bt index
        int b_  = row >> 11;                   // /2048
        int t   = row & (TT-1);
        float4 o = make_float4(acc[i][0], acc[i][1], acc[i][2], acc[i][3]);
        *(float4*)(out + ((size_t)(b_*HH + h)*TT + t)*DH + (tx<<2)) = o;
    }
}

// ---------------------------------------------------------------------------
// Kernel 2: causal flash attention with lag bias.
// grid (T/128, B*H), 128 threads; 1 thread = 1 query row, Q in registers.
// K/V streamed through smem in chunks of 32 rows.
// ---------------------------------------------------------------------------
#define BM 128
#define BN 32

__global__ __launch_bounds__(128) void attn_kernel() {
    __shared__ float4 Ks[BN][16];   // 32 x 64 floats
    __shared__ float4 Vs[BN][16];
    __shared__ float lagp[8];

    int bh  = blockIdx.y;          // b*H + h
    int h   = bh & (HH-1);
    int tid = threadIdx.x;
    int qi  = blockIdx.x * BM + tid;

    const float4* qp = (const float4*)(g_q + (size_t)bh*TT*DH);
    const float*  kp = g_k + (size_t)bh*TT*DH;
    const float*  vp = g_v + (size_t)bh*TT*DH;

    if (tid < MAXLAG+1) lagp[tid] = g_lagp[h*(MAXLAG+1) + tid];

    float4 q[16];
    #pragma unroll
    for (int i = 0; i < 16; i++) q[i] = qp[(size_t)qi*16 + i];

    float4 acc[16];
    #pragma unroll
    for (int i = 0; i < 16; i++) acc[i] = make_float4(0.f,0.f,0.f,0.f);
    float m = -1e30f, l = 0.f;
    const float scale = 0.125f;    // 1/sqrt(64)

    int nchunks = (blockIdx.x + 1) * (BM/BN);
    for (int c = 0; c < nchunks; c++) {
        int j0 = c * BN;
        __syncthreads();
        {   // cooperative load of K,V chunk (512 float4 each, 128 threads)
            const float4* kc = (const float4*)(kp + (size_t)j0*DH);
            const float4* vc = (const float4*)(vp + (size_t)j0*DH);
            #pragma unroll
            for (int i = 0; i < 4; i++) {
                int idx = tid + i*128;
                ((float4*)Ks)[idx] = kc[idx];
                ((float4*)Vs)[idx] = vc[idx];
            }
        }
        __syncthreads();

        if (j0 <= qi) {
            float s[BN];
            #pragma unroll
            for (int j = 0; j < BN; j++) s[j] = 0.f;
            #pragma unroll
            for (int d = 0; d < 16; d++) {
                float4 qv = q[d];
                #pragma unroll
                for (int j = 0; j < BN; j++) {
                    float4 kv = Ks[j][d];
                    s[j] += qv.x*kv.x + qv.y*kv.y + qv.z*kv.z + qv.w*kv.w;
                }
            }
            float mloc = m;
            #pragma unroll
            for (int j = 0; j < BN; j++) {
                int jj  = j0 + j;
                int lag = qi - jj;
                lag = lag < 0 ? 0 : (lag > MAXLAG ? MAXLAG : lag);
                s[j] = (jj <= qi) ? (s[j]*scale + lagp[lag]) : -1e30f;
                mloc = fmaxf(mloc, s[j]);
            }
            float corr = __expf(m - mloc);
            m = mloc;
            l *= corr;
            #pragma unroll
            for (int i = 0; i < 16; i++) {
                acc[i].x *= corr; acc[i].y *= corr; acc[i].z *= corr; acc[i].w *= corr;
            }
            #pragma unroll
            for (int j = 0; j < BN; j++) {
                float p = __expf(s[j] - m);
                l += p;
                #pragma unroll
                for (int d = 0; d < 16; d++) {
                    float4 vv = Vs[j][d];
                    acc[d].x += p*vv.x; acc[d].y += p*vv.y;
                    acc[d].z += p*vv.z; acc[d].w += p*vv.w;
                }
            }
        }
    }

    float inv = 1.f / l;
    int b_ = bh >> 3;
    float* op = g_att + ((size_t)(b_*TT + qi))*NINNER + h*DH;
    #pragma unroll
    for (int d = 0; d < 16; d++) {
        float4 o = acc[d];
        o.x *= inv; o.y *= inv; o.z *= inv; o.w *= inv;
        *(float4*)(op + d*4) = o;
    }
}

// ---------------------------------------------------------------------------
// Kernel 3: output GEMM: d_out = g_att @ Wo + bo   (4096x512 @ 512x512)
// ---------------------------------------------------------------------------
__global__ __launch_bounds__(256) void gemm_out_kernel(
    const float* __restrict__ Wo, const float* __restrict__ bo,
    float* __restrict__ Out)
{
    __shared__ float As[16][64];
    __shared__ float Bs[16][64];

    int tid = threadIdx.x;
    int tx = tid & 15, ty = tid >> 4;
    int row0 = blockIdx.y * 64, col0 = blockIdx.x * 64;

    float acc[4][4];
    #pragma unroll
    for (int i = 0; i < 4; i++)
        #pragma unroll
        for (int j = 0; j < 4; j++) acc[i][j] = 0.f;

    for (int k0 = 0; k0 < NINNER; k0 += 16) {
        {
            int r  = tid >> 2;
            int c4 = (tid & 3) << 2;
            float4 av = *(const float4*)(g_att + (size_t)(row0 + r)*NINNER + k0 + c4);
            As[c4+0][r] = av.x; As[c4+1][r] = av.y;
            As[c4+2][r] = av.z; As[c4+3][r] = av.w;
            int wr = tid >> 4;
            int wc = (tid & 15) << 2;
            *(float4*)&Bs[wr][wc] = *(const float4*)(Wo + (size_t)(k0+wr)*DD + col0 + wc);
        }
        __syncthreads();
        #pragma unroll
        for (int kk = 0; kk < 16; kk++) {
            float4 a = *(const float4*)&As[kk][ty<<2];
            float4 b = *(const float4*)&Bs[kk][tx<<2];
            acc[0][0] += a.x*b.x; acc[0][1] += a.x*b.y; acc[0][2] += a.x*b.z; acc[0][3] += a.x*b.w;
            acc[1][0] += a.y*b.x; acc[1][1] += a.y*b.y; acc[1][2] += a.y*b.z; acc[1][3] += a.y*b.w;
            acc[2][0] += a.z*b.x; acc[2][1] += a.z*b.y; acc[2][2] += a.z*b.z; acc[2][3] += a.z*b.w;
            acc[3][0] += a.w*b.x; acc[3][1] += a.w*b.y; acc[3][2] += a.w*b.z; acc[3][3] += a.w*b.w;
        }
        __syncthreads();
    }

    float4 bias = *(const float4*)(bo + col0 + (tx<<2));
    #pragma unroll
    for (int i = 0; i < 4; i++) {
        int row = row0 + (ty<<2) + i;
        float4 o = make_float4(acc[i][0]+bias.x, acc[i][1]+bias.y,
                               acc[i][2]+bias.z, acc[i][3]+bias.w);
        *(float4*)(Out + (size_t)row*DD + col0 + (tx<<2)) = o;
    }
}

// ---------------------------------------------------------------------------
extern "C" void kernel_launch(void* const* d_in, const int* in_sizes, int n_in,
                              void* d_out, int out_size) {
    const float* x  = (const float*)d_in[0];
    const float* Wq = (const float*)d_in[1];
    const float* Wk = (const float*)d_in[2];
    const float* Wv = (const float*)d_in[3];
    const float* Wo = (const float*)d_in[4];
    const float* bo = (const float*)d_in[5];
    const float* lw = (const float*)d_in[6];
    float* out = (float*)d_out;

    lag_softmax_kernel<<<1, 32>>>(lw);
    gemm_qkv_kernel<<<dim3(NINNER/64, BT/64, 3), 256>>>(x, Wq, Wk, Wv);
    attn_kernel<<<dim3(TT/BM, BB*HH), 128>>>();
    gemm_out_kernel<<<dim3(DD/64, BT/64), 256>>>(Wo, bo, out);
}

// round 3
// speedup vs baseline: 3.0431x; 3.0431x over previous
#include <cuda_runtime.h>
#include <cstdint>

#define BB 2
#define TT 2048
#define DD 512
#define HH 8
#define DH 64
#define NINNER 512
#define MAXLAG 5
#define BT (BB*TT)

// Scratch (device globals; no allocation allowed)
__device__ float g_q[BB*HH*TT*DH];     // tf32-rounded bits
__device__ float g_k[BB*HH*TT*DH];     // tf32-rounded bits
__device__ float g_v[BB*HH*TT*DH];     // tf32-rounded bits
__device__ float g_att[BT*NINNER];
__device__ float g_lagp[HH*(MAXLAG+1)];
__device__ float g_wt[4*DD*NINNER];    // W^T for Wq,Wk,Wv,Wo: WT[n][k] = W[k][n]

// ---------------------------------------------------------------------------
// helpers
// ---------------------------------------------------------------------------
static __device__ __forceinline__ uint32_t f2tf(float f) {
    uint32_t o;
    asm("cvt.rna.tf32.f32 %0, %1;" : "=r"(o) : "f"(f));
    return o;
}

// D += A(16x8) * B(8x8), tf32, row.col
static __device__ __forceinline__ void mma8(float* d, const uint32_t* a,
                                            uint32_t b0, uint32_t b1) {
    asm volatile(
        "mma.sync.aligned.m16n8k8.row.col.f32.tf32.tf32.f32 "
        "{%0,%1,%2,%3},{%4,%5,%6,%7},{%8,%9},{%0,%1,%2,%3};"
        : "+f"(d[0]), "+f"(d[1]), "+f"(d[2]), "+f"(d[3])
        : "r"(a[0]), "r"(a[1]), "r"(a[2]), "r"(a[3]), "r"(b0), "r"(b1));
}

// ---------------------------------------------------------------------------
// Kernel 0: softmax of lag_weights -> g_lagp  (8 heads x 6 lags)
// ---------------------------------------------------------------------------
__global__ void lag_softmax_kernel(const float* __restrict__ lw) {
    int h = threadIdx.x;
    if (h < HH) {
        float vals[MAXLAG+1];
        float m = -1e30f;
        #pragma unroll
        for (int i = 0; i <= MAXLAG; i++) { vals[i] = lw[h*(MAXLAG+1)+i]; m = fmaxf(m, vals[i]); }
        float s = 0.f;
        #pragma unroll
        for (int i = 0; i <= MAXLAG; i++) { vals[i] = __expf(vals[i]-m); s += vals[i]; }
        #pragma unroll
        for (int i = 0; i <= MAXLAG; i++) g_lagp[h*(MAXLAG+1)+i] = vals[i]/s;
    }
}

// ---------------------------------------------------------------------------
// Kernel T: transpose 4 weight matrices into g_wt (WT[n][k] = W[k][n])
// ---------------------------------------------------------------------------
__global__ __launch_bounds__(256) void transpose_w_kernel(
    const float* __restrict__ Wq, const float* __restrict__ Wk,
    const float* __restrict__ Wv, const float* __restrict__ Wo)
{
    __shared__ float tile[32][33];
    const float* W = (blockIdx.z == 0) ? Wq : (blockIdx.z == 1) ? Wk
                    : (blockIdx.z == 2) ? Wv : Wo;
    float* WT = g_wt + (size_t)blockIdx.z * DD * NINNER;
    int x0 = blockIdx.x * 32, y0 = blockIdx.y * 32;
    int tx = threadIdx.x & 31, ty = threadIdx.x >> 5;   // 32 x 8
    #pragma unroll
    for (int i = 0; i < 4; i++)
        tile[ty + i*8][tx] = W[(size_t)(y0 + ty + i*8) * NINNER + x0 + tx];
    __syncthreads();
    #pragma unroll
    for (int i = 0; i < 4; i++)
        WT[(size_t)(x0 + ty + i*8) * DD + y0 + tx] = tile[tx][ty + i*8];
}

// ---------------------------------------------------------------------------
// Shared GEMM mainloop: 128x128 CTA tile over K=512.
// A row-major [M,512], Bt row-major [N,512]. acc[mf][nf][4] per warp (32x64).
// smem strides: 36 floats/row (bank-bijective for frag reads).
// ---------------------------------------------------------------------------
#define GS 36

static __device__ __forceinline__ void mma_mainloop(
    const float* __restrict__ A, const float* __restrict__ Bt,
    int row0, int col0, float* As, float* Bs, float acc[2][8][4])
{
    int tid = threadIdx.x, wid = tid >> 5, lane = tid & 31;
    int g = lane >> 2, tig = lane & 3;
    int wm = wid & 3, wn = wid >> 2;          // warp tile: rows wm*32, cols wn*64
    int m0 = wm * 32, n0 = wn * 64;
    const uint32_t* Au = (const uint32_t*)As;
    const uint32_t* Bu = (const uint32_t*)Bs;

    for (int c = 0; c < 16; c++) {
        int k0 = c * 32;
        __syncthreads();
        #pragma unroll
        for (int i = 0; i < 4; i++) {
            int idx = tid + i * 256;           // 1024 float4 per matrix
            int r = idx >> 3, cf = idx & 7;
            float4 va = *(const float4*)(A  + (size_t)(row0 + r) * 512 + k0 + cf * 4);
            float4 vb = *(const float4*)(Bt + (size_t)(col0 + r) * 512 + k0 + cf * 4);
            uint4 ua = make_uint4(f2tf(va.x), f2tf(va.y), f2tf(va.z), f2tf(va.w));
            uint4 ub = make_uint4(f2tf(vb.x), f2tf(vb.y), f2tf(vb.z), f2tf(vb.w));
            *(uint4*)&As[r * GS + cf * 4] = ua;
            *(uint4*)&Bs[r * GS + cf * 4] = ub;
        }
        __syncthreads();
        #pragma unroll
        for (int kk = 0; kk < 4; kk++) {
            int k = kk * 8;
            uint32_t a[2][4];
            #pragma unroll
            for (int mf = 0; mf < 2; mf++) {
                int rb = m0 + mf * 16 + g;
                a[mf][0] = Au[rb * GS + k + tig];
                a[mf][1] = Au[(rb + 8) * GS + k + tig];
                a[mf][2] = Au[rb * GS + k + tig + 4];
                a[mf][3] = Au[(rb + 8) * GS + k + tig + 4];
            }
            #pragma unroll
            for (int nf = 0; nf < 8; nf++) {
                int nb = n0 + nf * 8 + g;
                uint32_t b0 = Bu[nb * GS + k + tig];
                uint32_t b1 = Bu[nb * GS + k + tig + 4];
                mma8(acc[0][nf], a[0], b0, b1);
                mma8(acc[1][nf], a[1], b0, b1);
            }
        }
    }
}

// ---------------------------------------------------------------------------
// Kernel 1: QKV GEMM. grid (4, 32, 3) x 256. Writes tf32-rounded [b,h,t,d].
// ---------------------------------------------------------------------------
__global__ __launch_bounds__(256) void gemm_qkv_mma(const float* __restrict__ x)
{
    __shared__ float As[128 * GS];
    __shared__ float Bs[128 * GS];
    int z = blockIdx.z;
    const float* Bt = g_wt + (size_t)z * DD * NINNER;
    float* out = (z == 0) ? g_q : (z == 1) ? g_k : g_v;
    int row0 = blockIdx.y * 128, col0 = blockIdx.x * 128;

    float acc[2][8][4];
    #pragma unroll
    for (int i = 0; i < 2; i++)
        #pragma unroll
        for (int j = 0; j < 8; j++)
            #pragma unroll
            for (int r = 0; r < 4; r++) acc[i][j][r] = 0.f;

    mma_mainloop(x, Bt, row0, col0, As, Bs, acc);

    int tid = threadIdx.x, wid = tid >> 5, lane = tid & 31;
    int g = lane >> 2, tig = lane & 3;
    int wm = wid & 3, wn = wid >> 2;
    int h = (col0 >> 6) + wn;
    #pragma unroll
    for (int mf = 0; mf < 2; mf++) {
        int r0 = row0 + wm * 32 + mf * 16 + g;
        int r1 = r0 + 8;
        int b0_ = r0 >> 11, t0 = r0 & (TT-1);
        int b1_ = r1 >> 11, t1 = r1 & (TT-1);
        float* p0 = out + ((size_t)(b0_*HH + h)*TT + t0)*DH;
        float* p1 = out + ((size_t)(b1_*HH + h)*TT + t1)*DH;
        #pragma unroll
        for (int nf = 0; nf < 8; nf++) {
            int d = nf * 8 + 2 * tig;
            float2 o0, o1;
            o0.x = __uint_as_float(f2tf(acc[mf][nf][0]));
            o0.y = __uint_as_float(f2tf(acc[mf][nf][1]));
            o1.x = __uint_as_float(f2tf(acc[mf][nf][2]));
            o1.y = __uint_as_float(f2tf(acc[mf][nf][3]));
            *(float2*)(p0 + d) = o0;
            *(float2*)(p1 + d) = o1;
        }
    }
}

// ---------------------------------------------------------------------------
// Kernel 3: output GEMM: d_out = g_att @ Wo + bo. grid (4, 32) x 256.
// ---------------------------------------------------------------------------
__global__ __launch_bounds__(256) void gemm_out_mma(
    const float* __restrict__ bo, float* __restrict__ Out)
{
    __shared__ float As[128 * GS];
    __shared__ float Bs[128 * GS];
    const float* Bt = g_wt + (size_t)3 * DD * NINNER;
    int row0 = blockIdx.y * 128, col0 = blockIdx.x * 128;

    float acc[2][8][4];
    #pragma unroll
    for (int i = 0; i < 2; i++)
        #pragma unroll
        for (int j = 0; j < 8; j++)
            #pragma unroll
            for (int r = 0; r < 4; r++) acc[i][j][r] = 0.f;

    mma_mainloop(g_att, Bt, row0, col0, As, Bs, acc);

    int tid = threadIdx.x, wid = tid >> 5, lane = tid & 31;
    int g = lane >> 2, tig = lane & 3;
    int wm = wid & 3, wn = wid >> 2;
    #pragma unroll
    for (int mf = 0; mf < 2; mf++) {
        int r0 = row0 + wm * 32 + mf * 16 + g;
        int r1 = r0 + 8;
        #pragma unroll
        for (int nf = 0; nf < 8; nf++) {
            int col = col0 + wn * 64 + nf * 8 + 2 * tig;
            float2 bias = *(const float2*)(bo + col);
            float2 o0, o1;
            o0.x = acc[mf][nf][0] + bias.x;
            o0.y = acc[mf][nf][1] + bias.y;
            o1.x = acc[mf][nf][2] + bias.x;
            o1.y = acc[mf][nf][3] + bias.y;
            *(float2*)(Out + (size_t)r0 * DD + col) = o0;
            *(float2*)(Out + (size_t)r1 * DD + col) = o1;
        }
    }
}

// ---------------------------------------------------------------------------
// Kernel 2: causal flash attention with lag bias — tf32 mma.sync.
// grid (16, 16) x 256. Warp owns 16 query rows; K/V chunks of 32.
// ---------------------------------------------------------------------------
#define KS_STR 68   // bank map 4g+tig  (bijective)
#define VS_STR 72   // bank map 8tig+g  (bijective)
#define PS_STR 36   // bank map 4g+tig  (bijective)

__global__ __launch_bounds__(256) void attn_mma() {
    __shared__ float Ks[32 * KS_STR];
    __shared__ float Vs[32 * VS_STR];
    __shared__ float Ps[8][16 * PS_STR];
    __shared__ float lagp[8];

    int bh = blockIdx.y, h = bh & (HH-1);
    int tid = threadIdx.x, wid = tid >> 5, lane = tid & 31;
    int g = lane >> 2, tig = lane & 3;
    int q0 = blockIdx.x * 128 + wid * 16;       // warp's first query row

    const float* qp = g_q + (size_t)bh * TT * DH;
    const float* kp = g_k + (size_t)bh * TT * DH;
    const float* vp = g_v + (size_t)bh * TT * DH;

    if (tid <= MAXLAG) lagp[tid] = g_lagp[h*(MAXLAG+1) + tid];

    // Q fragments (already tf32 bits): rows q0+g / q0+8+g, 8 k-frags over d=64
    uint32_t qa[8][4];
    #pragma unroll
    for (int kf = 0; kf < 8; kf++) {
        qa[kf][0] = __float_as_uint(qp[(size_t)(q0 + g     ) * DH + kf*8 + tig    ]);
        qa[kf][1] = __float_as_uint(qp[(size_t)(q0 + 8 + g ) * DH + kf*8 + tig    ]);
        qa[kf][2] = __float_as_uint(qp[(size_t)(q0 + g     ) * DH + kf*8 + tig + 4]);
        qa[kf][3] = __float_as_uint(qp[(size_t)(q0 + 8 + g ) * DH + kf*8 + tig + 4]);
    }

    float O[8][4];
    #pragma unroll
    for (int i = 0; i < 8; i++)
        #pragma unroll
        for (int r = 0; r < 4; r++) O[i][r] = 0.f;
    float mA = -1e30f, mB = -1e30f, lA = 0.f, lB = 0.f;

    int qiA = q0 + g, qiB = q0 + 8 + g;
    const float scale = 0.125f;
    float* Pw = Ps[wid];
    int nch = (blockIdx.x + 1) * 4;

    for (int c = 0; c < nch; c++) {
        int j0 = c * 32;
        __syncthreads();
        #pragma unroll
        for (int i = 0; i < 2; i++) {           // 512 float4 per matrix, 256 thr
            int idx = tid + i * 256;
            int r = idx >> 4, c4 = idx & 15;
            *(float4*)&Ks[r * KS_STR + c4*4] = *(const float4*)(kp + (size_t)(j0 + r)*DH + c4*4);
            *(float4*)&Vs[r * VS_STR + c4*4] = *(const float4*)(vp + (size_t)(j0 + r)*DH + c4*4);
        }
        __syncthreads();

        if (j0 <= q0 + 15) {
            // S = Q K^T  (16x32)
            float s[4][4];
            #pragma unroll
            for (int nf = 0; nf < 4; nf++)
                #pragma unroll
                for (int r = 0; r < 4; r++) s[nf][r] = 0.f;
            const uint32_t* Ku = (const uint32_t*)Ks;
            #pragma unroll
            for (int kf = 0; kf < 8; kf++) {
                int k = kf * 8;
                #pragma unroll
                for (int nf = 0; nf < 4; nf++) {
                    int nb = nf * 8 + g;
                    uint32_t b0 = Ku[nb * KS_STR + k + tig];
                    uint32_t b1 = Ku[nb * KS_STR + k + tig + 4];
                    mma8(s[nf], qa[kf], b0, b1);
                }
            }
            // scores + mask + lag bias
            float rmaxA = -1e30f, rmaxB = -1e30f;
            #pragma unroll
            for (int nf = 0; nf < 4; nf++) {
                int jc = j0 + nf * 8 + 2 * tig;
                #pragma unroll
                for (int u = 0; u < 2; u++) {
                    int jj = jc + u;
                    int lagA = qiA - jj; lagA = lagA < 0 ? 0 : (lagA > MAXLAG ? MAXLAG : lagA);
                    int lagB = qiB - jj; lagB = lagB < 0 ? 0 : (lagB > MAXLAG ? MAXLAG : lagB);
                    float vA = (jj <= qiA) ? (s[nf][u]   * scale + lagp[lagA]) : -1e30f;
                    float vB = (jj <= qiB) ? (s[nf][2+u] * scale + lagp[lagB]) : -1e30f;
                    s[nf][u]   = vA;  rmaxA = fmaxf(rmaxA, vA);
                    s[nf][2+u] = vB;  rmaxB = fmaxf(rmaxB, vB);
                }
            }
            rmaxA = fmaxf(rmaxA, __shfl_xor_sync(0xffffffffu, rmaxA, 1, 4));
            rmaxA = fmaxf(rmaxA, __shfl_xor_sync(0xffffffffu, rmaxA, 2, 4));
            rmaxB = fmaxf(rmaxB, __shfl_xor_sync(0xffffffffu, rmaxB, 1, 4));
            rmaxB = fmaxf(rmaxB, __shfl_xor_sync(0xffffffffu, rmaxB, 2, 4));
            float nmA = fmaxf(mA, rmaxA), nmB = fmaxf(mB, rmaxB);
            float corrA = __expf(mA - nmA), corrB = __expf(mB - nmB);
            mA = nmA; mB = nmB;
            #pragma unroll
            for (int nf = 0; nf < 8; nf++) {
                O[nf][0] *= corrA; O[nf][1] *= corrA;
                O[nf][2] *= corrB; O[nf][3] *= corrB;
            }
            float psA = 0.f, psB = 0.f;
            #pragma unroll
            for (int nf = 0; nf < 4; nf++) {
                float p0 = __expf(s[nf][0] - mA);
                float p1 = __expf(s[nf][1] - mA);
                float p2 = __expf(s[nf][2] - mB);
                float p3 = __expf(s[nf][3] - mB);
                psA += p0 + p1; psB += p2 + p3;
                int colc = nf * 8 + 2 * tig;
                Pw[g * PS_STR + colc]           = __uint_as_float(f2tf(p0));
                Pw[g * PS_STR + colc + 1]       = __uint_as_float(f2tf(p1));
                Pw[(g + 8) * PS_STR + colc]     = __uint_as_float(f2tf(p2));
                Pw[(g + 8) * PS_STR + colc + 1] = __uint_as_float(f2tf(p3));
            }
            psA += __shfl_xor_sync(0xffffffffu, psA, 1, 4);
            psA += __shfl_xor_sync(0xffffffffu, psA, 2, 4);
            psB += __shfl_xor_sync(0xffffffffu, psB, 1, 4);
            psB += __shfl_xor_sync(0xffffffffu, psB, 2, 4);
            lA = lA * corrA + psA;
            lB = lB * corrB + psB;
            __syncwarp();

            // O += P V  (16x32 @ 32x64)
            const uint32_t* Pu = (const uint32_t*)Pw;
            const uint32_t* Vu = (const uint32_t*)Vs;
            #pragma unroll
            for (int kf = 0; kf < 4; kf++) {
                int k = kf * 8;
                uint32_t a[4];
                a[0] = Pu[g * PS_STR + k + tig];
                a[1] = Pu[(g + 8) * PS_STR + k + tig];
                a[2] = Pu[g * PS_STR + k + tig + 4];
                a[3] = Pu[(g + 8) * PS_STR + k + tig + 4];
                #pragma unroll
                for (int nf = 0; nf < 8; nf++) {
                    uint32_t b0 = Vu[(k + tig) * VS_STR + nf * 8 + g];
                    uint32_t b1 = Vu[(k + tig + 4) * VS_STR + nf * 8 + g];
                    mma8(O[nf], a, b0, b1);
                }
            }
            __syncwarp();
        }
    }

    float invA = 1.f / lA, invB = 1.f / lB;
    int b_ = bh >> 3;
    float* pA = g_att + ((size_t)(b_ * TT + qiA)) * NINNER + h * DH;
    float* pB = g_att + ((size_t)(b_ * TT + qiB)) * NINNER + h * DH;
    #pragma unroll
    for (int nf = 0; nf < 8; nf++) {
        int d = nf * 8 + 2 * tig;
        float2 oA = make_float2(O[nf][0] * invA, O[nf][1] * invA);
        float2 oB = make_float2(O[nf][2] * invB, O[nf][3] * invB);
        *(float2*)(pA + d) = oA;
        *(float2*)(pB + d) = oB;
    }
}

// ---------------------------------------------------------------------------
extern "C" void kernel_launch(void* const* d_in, const int* in_sizes, int n_in,
                              void* d_out, int out_size) {
    const float* x  = (const float*)d_in[0];
    const float* Wq = (const float*)d_in[1];
    const float* Wk = (const float*)d_in[2];
    const float* Wv = (const float*)d_in[3];
    const float* Wo = (const float*)d_in[4];
    const float* bo = (const float*)d_in[5];
    const float* lw = (const float*)d_in[6];
    float* out = (float*)d_out;

    lag_softmax_kernel<<<1, 32>>>(lw);
    transpose_w_kernel<<<dim3(16, 16, 4), 256>>>(Wq, Wk, Wv, Wo);
    gemm_qkv_mma<<<dim3(NINNER/128, BT/128, 3), 256>>>(x);
    attn_mma<<<dim3(TT/128, BB*HH), 256>>>();
    gemm_out_mma<<<dim3(DD/128, BT/128), 256>>>(bo, out);
}

// round 4
// speedup vs baseline: 4.7433x; 1.5587x over previous
#include <cuda_runtime.h>
#include <cstdint>

#define BB 2
#define TT 2048
#define DD 512
#define HH 8
#define DH 64
#define NINNER 512
#define MAXLAG 5
#define BT (BB*TT)
#define NBH (BB*HH)
#define NQT 16          // query tiles of 128
#define MAXSEG 4        // key segments of 512

// Scratch (device globals; no allocation allowed)
__device__ float g_q[BB*HH*TT*DH];     // tf32-rounded bits
__device__ float g_k[BB*HH*TT*DH];
__device__ float g_v[BB*HH*TT*DH];
__device__ float g_att[BT*NINNER];
__device__ float g_lagp[HH*(MAXLAG+1)];
__device__ float g_wt[4*DD*NINNER];    // W^T for Wq,Wk,Wv,Wo
// split-KV partials
__device__ float g_pO[NBH*NQT*MAXSEG*128*64];
__device__ float g_pm[NBH*NQT*MAXSEG*128];
__device__ float g_pl[NBH*NQT*MAXSEG*128];

// work-unit table: 40 units per bh: (qtile, seg)
__device__ const uint8_t c_qt[40] = {0,1,2,3, 4,4,5,5,6,6,7,7,
    8,8,8,9,9,9,10,10,10,11,11,11,
    12,12,12,12,13,13,13,13,14,14,14,14,15,15,15,15};
__device__ const uint8_t c_sg[40] = {0,0,0,0, 0,1,0,1,0,1,0,1,
    0,1,2,0,1,2,0,1,2,0,1,2,
    0,1,2,3,0,1,2,3,0,1,2,3,0,1,2,3};

// ---------------------------------------------------------------------------
static __device__ __forceinline__ uint32_t f2tf(float f) {
    uint32_t o;
    asm("cvt.rna.tf32.f32 %0, %1;" : "=r"(o) : "f"(f));
    return o;
}
static __device__ __forceinline__ void mma8(float* d, const uint32_t* a,
                                            uint32_t b0, uint32_t b1) {
    asm volatile(
        "mma.sync.aligned.m16n8k8.row.col.f32.tf32.tf32.f32 "
        "{%0,%1,%2,%3},{%4,%5,%6,%7},{%8,%9},{%0,%1,%2,%3};"
        : "+f"(d[0]), "+f"(d[1]), "+f"(d[2]), "+f"(d[3])
        : "r"(a[0]), "r"(a[1]), "r"(a[2]), "r"(a[3]), "r"(b0), "r"(b1));
}

// ---------------------------------------------------------------------------
// Kernel 0: softmax of lag_weights
// ---------------------------------------------------------------------------
__global__ void lag_softmax_kernel(const float* __restrict__ lw) {
    int h = threadIdx.x;
    if (h < HH) {
        float vals[MAXLAG+1];
        float m = -1e30f;
        #pragma unroll
        for (int i = 0; i <= MAXLAG; i++) { vals[i] = lw[h*(MAXLAG+1)+i]; m = fmaxf(m, vals[i]); }
        float s = 0.f;
        #pragma unroll
        for (int i = 0; i <= MAXLAG; i++) { vals[i] = __expf(vals[i]-m); s += vals[i]; }
        #pragma unroll
        for (int i = 0; i <= MAXLAG; i++) g_lagp[h*(MAXLAG+1)+i] = vals[i]/s;
    }
}

// ---------------------------------------------------------------------------
// Kernel T: transpose 4 weight matrices into g_wt
// ---------------------------------------------------------------------------
__global__ __launch_bounds__(256) void transpose_w_kernel(
    const float* __restrict__ Wq, const float* __restrict__ Wk,
    const float* __restrict__ Wv, const float* __restrict__ Wo)
{
    __shared__ float tile[32][33];
    const float* W = (blockIdx.z == 0) ? Wq : (blockIdx.z == 1) ? Wk
                    : (blockIdx.z == 2) ? Wv : Wo;
    float* WT = g_wt + (size_t)blockIdx.z * DD * NINNER;
    int x0 = blockIdx.x * 32, y0 = blockIdx.y * 32;
    int tx = threadIdx.x & 31, ty = threadIdx.x >> 5;
    #pragma unroll
    for (int i = 0; i < 4; i++)
        tile[ty + i*8][tx] = W[(size_t)(y0 + ty + i*8) * NINNER + x0 + tx];
    __syncthreads();
    #pragma unroll
    for (int i = 0; i < 4; i++)
        WT[(size_t)(x0 + ty + i*8) * DD + y0 + tx] = tile[tx][ty + i*8];
}

// ---------------------------------------------------------------------------
// GEMM mainloop, software-pipelined (prefetch next K-chunk during mma).
// ---------------------------------------------------------------------------
#define GS 36

static __device__ __forceinline__ void mma_mainloop(
    const float* __restrict__ A, const float* __restrict__ Bt,
    int row0, int col0, float* As, float* Bs, float acc[2][8][4])
{
    int tid = threadIdx.x, wid = tid >> 5, lane = tid & 31;
    int g = lane >> 2, tig = lane & 3;
    int wm = wid & 3, wn = wid >> 2;
    int m0 = wm * 32, n0 = wn * 64;
    const uint32_t* Au = (const uint32_t*)As;
    const uint32_t* Bu = (const uint32_t*)Bs;

    int r_ = tid >> 3, cf_ = tid & 7;          // per-thread fixed (row, col4)
    const float* pa = A  + (size_t)(row0 + r_) * 512 + cf_ * 4;
    const float* pb = Bt + (size_t)(col0 + r_) * 512 + cf_ * 4;

    float4 ra[4], rb[4];
    #pragma unroll
    for (int i = 0; i < 4; i++) {              // rows r_, r_+32, r_+64, r_+96
        ra[i] = *(const float4*)(pa + (size_t)i * 32 * 512);
        rb[i] = *(const float4*)(pb + (size_t)i * 32 * 512);
    }

    for (int c = 0; c < 16; c++) {
        __syncthreads();
        #pragma unroll
        for (int i = 0; i < 4; i++) {
            int r = r_ + i * 32;
            *(uint4*)&As[r * GS + cf_ * 4] =
                make_uint4(f2tf(ra[i].x), f2tf(ra[i].y), f2tf(ra[i].z), f2tf(ra[i].w));
            *(uint4*)&Bs[r * GS + cf_ * 4] =
                make_uint4(f2tf(rb[i].x), f2tf(rb[i].y), f2tf(rb[i].z), f2tf(rb[i].w));
        }
        __syncthreads();
        if (c < 15) {
            int k0 = (c + 1) * 32;
            #pragma unroll
            for (int i = 0; i < 4; i++) {
                ra[i] = *(const float4*)(pa + (size_t)i * 32 * 512 + k0);
                rb[i] = *(const float4*)(pb + (size_t)i * 32 * 512 + k0);
            }
        }
        #pragma unroll
        for (int kk = 0; kk < 4; kk++) {
            int k = kk * 8;
            uint32_t a[2][4];
            #pragma unroll
            for (int mf = 0; mf < 2; mf++) {
                int rb2 = m0 + mf * 16 + g;
                a[mf][0] = Au[rb2 * GS + k + tig];
                a[mf][1] = Au[(rb2 + 8) * GS + k + tig];
                a[mf][2] = Au[rb2 * GS + k + tig + 4];
                a[mf][3] = Au[(rb2 + 8) * GS + k + tig + 4];
            }
            #pragma unroll
            for (int nf = 0; nf < 8; nf++) {
                int nb = n0 + nf * 8 + g;
                uint32_t b0 = Bu[nb * GS + k + tig];
                uint32_t b1 = Bu[nb * GS + k + tig + 4];
                mma8(acc[0][nf], a[0], b0, b1);
                mma8(acc[1][nf], a[1], b0, b1);
            }
        }
    }
}

// ---------------------------------------------------------------------------
// Kernel 1: QKV GEMM. grid (4, 32, 3) x 256. Writes tf32-rounded [b,h,t,d].
// ---------------------------------------------------------------------------
__global__ __launch_bounds__(256) void gemm_qkv_mma(const float* __restrict__ x)
{
    __shared__ float As[128 * GS];
    __shared__ float Bs[128 * GS];
    int z = blockIdx.z;
    const float* Bt = g_wt + (size_t)z * DD * NINNER;
    float* out = (z == 0) ? g_q : (z == 1) ? g_k : g_v;
    int row0 = blockIdx.y * 128, col0 = blockIdx.x * 128;

    float acc[2][8][4];
    #pragma unroll
    for (int i = 0; i < 2; i++)
        #pragma unroll
        for (int j = 0; j < 8; j++)
            #pragma unroll
            for (int r = 0; r < 4; r++) acc[i][j][r] = 0.f;

    mma_mainloop(x, Bt, row0, col0, As, Bs, acc);

    int tid = threadIdx.x, wid = tid >> 5, lane = tid & 31;
    int g = lane >> 2, tig = lane & 3;
    int wm = wid & 3, wn = wid >> 2;
    int h = (col0 >> 6) + wn;
    #pragma unroll
    for (int mf = 0; mf < 2; mf++) {
        int r0 = row0 + wm * 32 + mf * 16 + g;
        int r1 = r0 + 8;
        int b0_ = r0 >> 11, t0 = r0 & (TT-1);
        int b1_ = r1 >> 11, t1 = r1 & (TT-1);
        float* p0 = out + ((size_t)(b0_*HH + h)*TT + t0)*DH;
        float* p1 = out + ((size_t)(b1_*HH + h)*TT + t1)*DH;
        #pragma unroll
        for (int nf = 0; nf < 8; nf++) {
            int d = nf * 8 + 2 * tig;
            float2 o0, o1;
            o0.x = __uint_as_float(f2tf(acc[mf][nf][0]));
            o0.y = __uint_as_float(f2tf(acc[mf][nf][1]));
            o1.x = __uint_as_float(f2tf(acc[mf][nf][2]));
            o1.y = __uint_as_float(f2tf(acc[mf][nf][3]));
            *(float2*)(p0 + d) = o0;
            *(float2*)(p1 + d) = o1;
        }
    }
}

// ---------------------------------------------------------------------------
// Kernel 3: output GEMM: d_out = g_att @ Wo + bo. grid (4, 32) x 256.
// ---------------------------------------------------------------------------
__global__ __launch_bounds__(256) void gemm_out_mma(
    const float* __restrict__ bo, float* __restrict__ Out)
{
    __shared__ float As[128 * GS];
    __shared__ float Bs[128 * GS];
    const float* Bt = g_wt + (size_t)3 * DD * NINNER;
    int row0 = blockIdx.y * 128, col0 = blockIdx.x * 128;

    float acc[2][8][4];
    #pragma unroll
    for (int i = 0; i < 2; i++)
        #pragma unroll
        for (int j = 0; j < 8; j++)
            #pragma unroll
            for (int r = 0; r < 4; r++) acc[i][j][r] = 0.f;

    mma_mainloop(g_att, Bt, row0, col0, As, Bs, acc);

    int tid = threadIdx.x, wid = tid >> 5, lane = tid & 31;
    int g = lane >> 2, tig = lane & 3;
    int wm = wid & 3, wn = wid >> 2;
    #pragma unroll
    for (int mf = 0; mf < 2; mf++) {
        int r0 = row0 + wm * 32 + mf * 16 + g;
        int r1 = r0 + 8;
        #pragma unroll
        for (int nf = 0; nf < 8; nf++) {
            int col = col0 + wn * 64 + nf * 8 + 2 * tig;
            float2 bias = *(const float2*)(bo + col);
            float2 o0, o1;
            o0.x = acc[mf][nf][0] + bias.x;
            o0.y = acc[mf][nf][1] + bias.y;
            o1.x = acc[mf][nf][2] + bias.x;
            o1.y = acc[mf][nf][3] + bias.y;
            *(float2*)(Out + (size_t)r0 * DD + col) = o0;
            *(float2*)(Out + (size_t)r1 * DD + col) = o1;
        }
    }
}

// ---------------------------------------------------------------------------
// Kernel 2a: split-KV causal attention with lag bias — tf32 mma.sync.
// grid (40, 16) x 256. Work unit = (qtile of 128 rows, key segment of <=512).
// Writes unnormalized partials (O, m, l).
// ---------------------------------------------------------------------------
#define KS_STR 68
#define VS_STR 72
#define PS_STR 36

__global__ __launch_bounds__(256) void attn_mma() {
    __shared__ float Ks[32 * KS_STR];
    __shared__ float Vs[32 * VS_STR];
    __shared__ float Ps[8][16 * PS_STR];
    __shared__ float lagp[8];

    int u = blockIdx.x;
    int qt = c_qt[u], seg = c_sg[u];
    int bh = blockIdx.y, h = bh & (HH-1);
    int tid = threadIdx.x, wid = tid >> 5, lane = tid & 31;
    int g = lane >> 2, tig = lane & 3;
    int q0 = qt * 128 + wid * 16;

    int kstart = seg * 512;
    int kend = min((seg + 1) * 512, (qt + 1) * 128);
    int nch = (kend - kstart) >> 5;

    const float* qp = g_q + (size_t)bh * TT * DH;
    const float* kp = g_k + (size_t)bh * TT * DH;
    const float* vp = g_v + (size_t)bh * TT * DH;

    if (tid <= MAXLAG) lagp[tid] = g_lagp[h*(MAXLAG+1) + tid];

    uint32_t qa[8][4];
    #pragma unroll
    for (int kf = 0; kf < 8; kf++) {
        qa[kf][0] = __float_as_uint(qp[(size_t)(q0 + g    ) * DH + kf*8 + tig    ]);
        qa[kf][1] = __float_as_uint(qp[(size_t)(q0 + 8 + g) * DH + kf*8 + tig    ]);
        qa[kf][2] = __float_as_uint(qp[(size_t)(q0 + g    ) * DH + kf*8 + tig + 4]);
        qa[kf][3] = __float_as_uint(qp[(size_t)(q0 + 8 + g) * DH + kf*8 + tig + 4]);
    }

    float O[8][4];
    #pragma unroll
    for (int i = 0; i < 8; i++)
        #pragma unroll
        for (int r = 0; r < 4; r++) O[i][r] = 0.f;
    float mA = -1e30f, mB = -1e30f, lA = 0.f, lB = 0.f;

    int qiA = q0 + g, qiB = q0 + 8 + g;
    const float scale = 0.125f;
    float* Pw = Ps[wid];

    // per-thread fixed K/V load slots (2 float4 each)
    int r_ = tid >> 4, c4_ = tid & 15;
    float4 rk[2], rv[2];
    #pragma unroll
    for (int i = 0; i < 2; i++) {
        int r = r_ + i * 16;
        rk[i] = *(const float4*)(kp + (size_t)(kstart + r)*DH + c4_*4);
        rv[i] = *(const float4*)(vp + (size_t)(kstart + r)*DH + c4_*4);
    }

    for (int c = 0; c < nch; c++) {
        int j0 = kstart + c * 32;
        __syncthreads();
        #pragma unroll
        for (int i = 0; i < 2; i++) {
            int r = r_ + i * 16;
            *(float4*)&Ks[r * KS_STR + c4_*4] = rk[i];
            *(float4*)&Vs[r * VS_STR + c4_*4] = rv[i];
        }
        __syncthreads();
        if (c + 1 < nch) {
            int jn = j0 + 32;
            #pragma unroll
            for (int i = 0; i < 2; i++) {
                int r = r_ + i * 16;
                rk[i] = *(const float4*)(kp + (size_t)(jn + r)*DH + c4_*4);
                rv[i] = *(const float4*)(vp + (size_t)(jn + r)*DH + c4_*4);
            }
        }

        if (j0 <= q0 + 15) {
            float s[4][4];
            #pragma unroll
            for (int nf = 0; nf < 4; nf++)
                #pragma unroll
                for (int r = 0; r < 4; r++) s[nf][r] = 0.f;
            const uint32_t* Ku = (const uint32_t*)Ks;
            #pragma unroll
            for (int kf = 0; kf < 8; kf++) {
                int k = kf * 8;
                #pragma unroll
                for (int nf = 0; nf < 4; nf++) {
                    int nb = nf * 8 + g;
                    uint32_t b0 = Ku[nb * KS_STR + k + tig];
                    uint32_t b1 = Ku[nb * KS_STR + k + tig + 4];
                    mma8(s[nf], qa[kf], b0, b1);
                }
            }
            float rmaxA = -1e30f, rmaxB = -1e30f;
            #pragma unroll
            for (int nf = 0; nf < 4; nf++) {
                int jc = j0 + nf * 8 + 2 * tig;
                #pragma unroll
                for (int uu = 0; uu < 2; uu++) {
                    int jj = jc + uu;
                    int lagA = qiA - jj; lagA = lagA < 0 ? 0 : (lagA > MAXLAG ? MAXLAG : lagA);
                    int lagB = qiB - jj; lagB = lagB < 0 ? 0 : (lagB > MAXLAG ? MAXLAG : lagB);
                    float vA = (jj <= qiA) ? (s[nf][uu]   * scale + lagp[lagA]) : -1e30f;
                    float vB = (jj <= qiB) ? (s[nf][2+uu] * scale + lagp[lagB]) : -1e30f;
                    s[nf][uu]   = vA;  rmaxA = fmaxf(rmaxA, vA);
                    s[nf][2+uu] = vB;  rmaxB = fmaxf(rmaxB, vB);
                }
            }
            rmaxA = fmaxf(rmaxA, __shfl_xor_sync(0xffffffffu, rmaxA, 1, 4));
            rmaxA = fmaxf(rmaxA, __shfl_xor_sync(0xffffffffu, rmaxA, 2, 4));
            rmaxB = fmaxf(rmaxB, __shfl_xor_sync(0xffffffffu, rmaxB, 1, 4));
            rmaxB = fmaxf(rmaxB, __shfl_xor_sync(0xffffffffu, rmaxB, 2, 4));
            float nmA = fmaxf(mA, rmaxA), nmB = fmaxf(mB, rmaxB);
            float corrA = __expf(mA - nmA), corrB = __expf(mB - nmB);
            mA = nmA; mB = nmB;
            #pragma unroll
            for (int nf = 0; nf < 8; nf++) {
                O[nf][0] *= corrA; O[nf][1] *= corrA;
                O[nf][2] *= corrB; O[nf][3] *= corrB;
            }
            float psA = 0.f, psB = 0.f;
            #pragma unroll
            for (int nf = 0; nf < 4; nf++) {
                float p0 = __expf(s[nf][0] - mA);
                float p1 = __expf(s[nf][1] - mA);
                float p2 = __expf(s[nf][2] - mB);
                float p3 = __expf(s[nf][3] - mB);
                psA += p0 + p1; psB += p2 + p3;
                int colc = nf * 8 + 2 * tig;
                Pw[g * PS_STR + colc]           = __uint_as_float(f2tf(p0));
                Pw[g * PS_STR + colc + 1]       = __uint_as_float(f2tf(p1));
                Pw[(g + 8) * PS_STR + colc]     = __uint_as_float(f2tf(p2));
                Pw[(g + 8) * PS_STR + colc + 1] = __uint_as_float(f2tf(p3));
            }
            psA += __shfl_xor_sync(0xffffffffu, psA, 1, 4);
            psA += __shfl_xor_sync(0xffffffffu, psA, 2, 4);
            psB += __shfl_xor_sync(0xffffffffu, psB, 1, 4);
            psB += __shfl_xor_sync(0xffffffffu, psB, 2, 4);
            lA = lA * corrA + psA;
            lB = lB * corrB + psB;
            __syncwarp();

            const uint32_t* Pu = (const uint32_t*)Pw;
            const uint32_t* Vu = (const uint32_t*)Vs;
            #pragma unroll
            for (int kf = 0; kf < 4; kf++) {
                int k = kf * 8;
                uint32_t a[4];
                a[0] = Pu[g * PS_STR + k + tig];
                a[1] = Pu[(g + 8) * PS_STR + k + tig];
                a[2] = Pu[g * PS_STR + k + tig + 4];
                a[3] = Pu[(g + 8) * PS_STR + k + tig + 4];
                #pragma unroll
                for (int nf = 0; nf < 8; nf++) {
                    uint32_t b0 = Vu[(k + tig) * VS_STR + nf * 8 + g];
                    uint32_t b1 = Vu[(k + tig + 4) * VS_STR + nf * 8 + g];
                    mma8(O[nf], a, b0, b1);
                }
            }
            __syncwarp();
        }
    }

    // write unnormalized partials
    int base = (bh * NQT + qt) * MAXSEG + seg;
    float* pO = g_pO + (size_t)base * 128 * 64;
    int rA = wid * 16 + g, rB = rA + 8;
    #pragma unroll
    for (int nf = 0; nf < 8; nf++) {
        int d = nf * 8 + 2 * tig;
        *(float2*)(pO + rA * 64 + d) = make_float2(O[nf][0], O[nf][1]);
        *(float2*)(pO + rB * 64 + d) = make_float2(O[nf][2], O[nf][3]);
    }
    if (tig == 0) {
        g_pm[base * 128 + rA] = mA; g_pl[base * 128 + rA] = lA;
        g_pm[base * 128 + rB] = mB; g_pl[base * 128 + rB] = lB;
    }
}

// ---------------------------------------------------------------------------
// Kernel 2b: combine partials -> g_att.  grid (16 qt, 16 bh) x 256.
// ---------------------------------------------------------------------------
__global__ __launch_bounds__(256) void attn_combine() {
    int qt = blockIdx.x, bh = blockIdx.y;
    int h = bh & (HH-1), b_ = bh >> 3;
    int nseg = (qt >> 2) + 1;
    int base0 = (bh * NQT + qt) * MAXSEG;
    int tid = threadIdx.x;

    #pragma unroll
    for (int it = 0; it < 8; it++) {
        int p = tid + it * 256;          // 2048 (row, d4) pairs
        int r = p >> 4, d4 = p & 15;
        float m = -1e30f;
        for (int s = 0; s < nseg; s++)
            m = fmaxf(m, g_pm[(base0 + s) * 128 + r]);
        float w[MAXSEG];
        float L = 0.f;
        for (int s = 0; s < nseg; s++) {
            w[s] = __expf(g_pm[(base0 + s) * 128 + r] - m);
            L += w[s] * g_pl[(base0 + s) * 128 + r];
        }
        float inv = 1.f / L;
        float4 a = make_float4(0.f, 0.f, 0.f, 0.f);
        for (int s = 0; s < nseg; s++) {
            const float4 v = *(const float4*)(g_pO +
                ((size_t)(base0 + s) * 128 + r) * 64 + d4 * 4);
            a.x += w[s] * v.x; a.y += w[s] * v.y;
            a.z += w[s] * v.z; a.w += w[s] * v.w;
        }
        a.x *= inv; a.y *= inv; a.z *= inv; a.w *= inv;
        int qi = qt * 128 + r;
        *(float4*)(g_att + ((size_t)(b_ * TT + qi)) * NINNER + h * DH + d4 * 4) = a;
    }
}

// ---------------------------------------------------------------------------
extern "C" void kernel_launch(void* const* d_in, const int* in_sizes, int n_in,
                              void* d_out, int out_size) {
    const float* x  = (const float*)d_in[0];
    const float* Wq = (const float*)d_in[1];
    const float* Wk = (const float*)d_in[2];
    const float* Wv = (const float*)d_in[3];
    const float* Wo = (const float*)d_in[4];
    const float* bo = (const float*)d_in[5];
    const float* lw = (const float*)d_in[6];
    float* out = (float*)d_out;

    lag_softmax_kernel<<<1, 32>>>(lw);
    transpose_w_kernel<<<dim3(16, 16, 4), 256>>>(Wq, Wk, Wv, Wo);
    gemm_qkv_mma<<<dim3(NINNER/128, BT/128, 3), 256>>>(x);
    attn_mma<<<dim3(40, NBH), 256>>>();
    attn_combine<<<dim3(NQT, NBH), 256>>>();
    gemm_out_mma<<<dim3(DD/128, BT/128), 256>>>(bo, out);
}

// round 5
// speedup vs baseline: 4.9724x; 1.0483x over previous
#include <cuda_runtime.h>
#include <cstdint>

#define BB 2
#define TT 2048
#define DD 512
#define HH 8
#define DH 64
#define NINNER 512
#define MAXLAG 5
#define BT (BB*TT)
#define NBH (BB*HH)
#define NQT 16
#define MAXSEG 4

// Scratch (device globals; no allocation allowed)
__device__ float g_q[BB*HH*TT*DH];     // tf32-rounded bits
__device__ float g_k[BB*HH*TT*DH];
__device__ float g_v[BB*HH*TT*DH];
__device__ float g_att[BT*NINNER];
__device__ float g_lagp[HH*(MAXLAG+1)];
__device__ float g_wt[4*DD*NINNER];    // W^T for Wq,Wk,Wv,Wo
// split-KV partials
__device__ float g_pO[NBH*NQT*MAXSEG*128*64];
__device__ float g_pm[NBH*NQT*MAXSEG*128];
__device__ float g_pl[NBH*NQT*MAXSEG*128];

// work-unit table: 40 units per bh: (qtile, seg)
__device__ const uint8_t c_qt[40] = {0,1,2,3, 4,4,5,5,6,6,7,7,
    8,8,8,9,9,9,10,10,10,11,11,11,
    12,12,12,12,13,13,13,13,14,14,14,14,15,15,15,15};
__device__ const uint8_t c_sg[40] = {0,0,0,0, 0,1,0,1,0,1,0,1,
    0,1,2,0,1,2,0,1,2,0,1,2,
    0,1,2,3,0,1,2,3,0,1,2,3,0,1,2,3};

// ---------------------------------------------------------------------------
static __device__ __forceinline__ uint32_t f2tf(float f) {
    uint32_t o;
    asm("cvt.rna.tf32.f32 %0, %1;" : "=r"(o) : "f"(f));
    return o;
}
static __device__ __forceinline__ void mma8(float* d, const uint32_t* a,
                                            uint32_t b0, uint32_t b1) {
    asm volatile(
        "mma.sync.aligned.m16n8k8.row.col.f32.tf32.tf32.f32 "
        "{%0,%1,%2,%3},{%4,%5,%6,%7},{%8,%9},{%0,%1,%2,%3};"
        : "+f"(d[0]), "+f"(d[1]), "+f"(d[2]), "+f"(d[3])
        : "r"(a[0]), "r"(a[1]), "r"(a[2]), "r"(a[3]), "r"(b0), "r"(b1));
}
static __device__ __forceinline__ uint32_t smem_u32(const void* p) {
    uint32_t a;
    asm("{ .reg .u64 t; cvta.to.shared.u64 t, %1; cvt.u32.u64 %0, t; }" : "=r"(a) : "l"(p));
    return a;
}
#define CP_ASYNC16(dst, src) \
    asm volatile("cp.async.cg.shared.global [%0], [%1], 16;" :: "r"(dst), "l"(src))
#define CP_COMMIT() asm volatile("cp.async.commit_group;" ::: "memory")
#define CP_WAIT0()  asm volatile("cp.async.wait_group 0;" ::: "memory")

// ---------------------------------------------------------------------------
// Kernel 0: softmax of lag_weights
// ---------------------------------------------------------------------------
__global__ void lag_softmax_kernel(const float* __restrict__ lw) {
    int h = threadIdx.x;
    if (h < HH) {
        float vals[MAXLAG+1];
        float m = -1e30f;
        #pragma unroll
        for (int i = 0; i <= MAXLAG; i++) { vals[i] = lw[h*(MAXLAG+1)+i]; m = fmaxf(m, vals[i]); }
        float s = 0.f;
        #pragma unroll
        for (int i = 0; i <= MAXLAG; i++) { vals[i] = __expf(vals[i]-m); s += vals[i]; }
        #pragma unroll
        for (int i = 0; i <= MAXLAG; i++) g_lagp[h*(MAXLAG+1)+i] = vals[i]/s;
    }
}

// ---------------------------------------------------------------------------
// Kernel T: transpose 4 weight matrices into g_wt
// ---------------------------------------------------------------------------
__global__ __launch_bounds__(256) void transpose_w_kernel(
    const float* __restrict__ Wq, const float* __restrict__ Wk,
    const float* __restrict__ Wv, const float* __restrict__ Wo)
{
    __shared__ float tile[32][33];
    const float* W = (blockIdx.z == 0) ? Wq : (blockIdx.z == 1) ? Wk
                    : (blockIdx.z == 2) ? Wv : Wo;
    float* WT = g_wt + (size_t)blockIdx.z * DD * NINNER;
    int x0 = blockIdx.x * 32, y0 = blockIdx.y * 32;
    int tx = threadIdx.x & 31, ty = threadIdx.x >> 5;
    #pragma unroll
    for (int i = 0; i < 4; i++)
        tile[ty + i*8][tx] = W[(size_t)(y0 + ty + i*8) * NINNER + x0 + tx];
    __syncthreads();
    #pragma unroll
    for (int i = 0; i < 4; i++)
        WT[(size_t)(x0 + ty + i*8) * DD + y0 + tx] = tile[tx][ty + i*8];
}

// ---------------------------------------------------------------------------
// GEMM mainloop: double-buffered smem, register prefetch, 1 sync per chunk.
// ---------------------------------------------------------------------------
#define GS 36

static __device__ __forceinline__ void mma_mainloop(
    const float* __restrict__ A, const float* __restrict__ Bt,
    int row0, int col0, float* As, float* Bs, float acc[2][8][4])
{
    int tid = threadIdx.x, wid = tid >> 5, lane = tid & 31;
    int g = lane >> 2, tig = lane & 3;
    int wm = wid & 3, wn = wid >> 2;
    int m0 = wm * 32, n0 = wn * 64;

    int r_ = tid >> 3, cf_ = tid & 7;
    const float* pa = A  + (size_t)(row0 + r_) * 512 + cf_ * 4;
    const float* pb = Bt + (size_t)(col0 + r_) * 512 + cf_ * 4;

    float4 ra[4], rb[4];
    #pragma unroll
    for (int i = 0; i < 4; i++) {
        ra[i] = *(const float4*)(pa + (size_t)i * 32 * 512);
        rb[i] = *(const float4*)(pb + (size_t)i * 32 * 512);
    }

    for (int c = 0; c < 16; c++) {
        float* Asb = As + (c & 1) * 128 * GS;
        float* Bsb = Bs + (c & 1) * 128 * GS;
        #pragma unroll
        for (int i = 0; i < 4; i++) {
            int r = r_ + i * 32;
            *(uint4*)&Asb[r * GS + cf_ * 4] =
                make_uint4(f2tf(ra[i].x), f2tf(ra[i].y), f2tf(ra[i].z), f2tf(ra[i].w));
            *(uint4*)&Bsb[r * GS + cf_ * 4] =
                make_uint4(f2tf(rb[i].x), f2tf(rb[i].y), f2tf(rb[i].z), f2tf(rb[i].w));
        }
        __syncthreads();
        if (c < 15) {
            int k0 = (c + 1) * 32;
            #pragma unroll
            for (int i = 0; i < 4; i++) {
                ra[i] = *(const float4*)(pa + (size_t)i * 32 * 512 + k0);
                rb[i] = *(const float4*)(pb + (size_t)i * 32 * 512 + k0);
            }
        }
        const uint32_t* Au = (const uint32_t*)Asb;
        const uint32_t* Bu = (const uint32_t*)Bsb;
        #pragma unroll
        for (int kk = 0; kk < 4; kk++) {
            int k = kk * 8;
            uint32_t a[2][4];
            #pragma unroll
            for (int mf = 0; mf < 2; mf++) {
                int rb2 = m0 + mf * 16 + g;
                a[mf][0] = Au[rb2 * GS + k + tig];
                a[mf][1] = Au[(rb2 + 8) * GS + k + tig];
                a[mf][2] = Au[rb2 * GS + k + tig + 4];
                a[mf][3] = Au[(rb2 + 8) * GS + k + tig + 4];
            }
            #pragma unroll
            for (int nf = 0; nf < 8; nf++) {
                int nb = n0 + nf * 8 + g;
                uint32_t b0 = Bu[nb * GS + k + tig];
                uint32_t b1 = Bu[nb * GS + k + tig + 4];
                mma8(acc[0][nf], a[0], b0, b1);
                mma8(acc[1][nf], a[1], b0, b1);
            }
        }
    }
}

// ---------------------------------------------------------------------------
// Kernel 1: QKV GEMM. grid (4, 32, 3) x 256. Writes tf32-rounded [b,h,t,d].
// ---------------------------------------------------------------------------
__global__ __launch_bounds__(256) void gemm_qkv_mma(const float* __restrict__ x)
{
    __shared__ float As[2 * 128 * GS];
    __shared__ float Bs[2 * 128 * GS];
    int z = blockIdx.z;
    const float* Bt = g_wt + (size_t)z * DD * NINNER;
    float* out = (z == 0) ? g_q : (z == 1) ? g_k : g_v;
    int row0 = blockIdx.y * 128, col0 = blockIdx.x * 128;

    float acc[2][8][4];
    #pragma unroll
    for (int i = 0; i < 2; i++)
        #pragma unroll
        for (int j = 0; j < 8; j++)
            #pragma unroll
            for (int r = 0; r < 4; r++) acc[i][j][r] = 0.f;

    mma_mainloop(x, Bt, row0, col0, As, Bs, acc);

    int tid = threadIdx.x, wid = tid >> 5, lane = tid & 31;
    int g = lane >> 2, tig = lane & 3;
    int wm = wid & 3, wn = wid >> 2;
    int h = (col0 >> 6) + wn;
    #pragma unroll
    for (int mf = 0; mf < 2; mf++) {
        int r0 = row0 + wm * 32 + mf * 16 + g;
        int r1 = r0 + 8;
        int b0_ = r0 >> 11, t0 = r0 & (TT-1);
        int b1_ = r1 >> 11, t1 = r1 & (TT-1);
        float* p0 = out + ((size_t)(b0_*HH + h)*TT + t0)*DH;
        float* p1 = out + ((size_t)(b1_*HH + h)*TT + t1)*DH;
        #pragma unroll
        for (int nf = 0; nf < 8; nf++) {
            int d = nf * 8 + 2 * tig;
            float2 o0, o1;
            o0.x = __uint_as_float(f2tf(acc[mf][nf][0]));
            o0.y = __uint_as_float(f2tf(acc[mf][nf][1]));
            o1.x = __uint_as_float(f2tf(acc[mf][nf][2]));
            o1.y = __uint_as_float(f2tf(acc[mf][nf][3]));
            *(float2*)(p0 + d) = o0;
            *(float2*)(p1 + d) = o1;
        }
    }
}

// ---------------------------------------------------------------------------
// Kernel 3: output GEMM: d_out = g_att @ Wo + bo. grid (4, 32) x 256.
// ---------------------------------------------------------------------------
__global__ __launch_bounds__(256) void gemm_out_mma(
    const float* __restrict__ bo, float* __restrict__ Out)
{
    __shared__ float As[2 * 128 * GS];
    __shared__ float Bs[2 * 128 * GS];
    const float* Bt = g_wt + (size_t)3 * DD * NINNER;
    int row0 = blockIdx.y * 128, col0 = blockIdx.x * 128;

    float acc[2][8][4];
    #pragma unroll
    for (int i = 0; i < 2; i++)
        #pragma unroll
        for (int j = 0; j < 8; j++)
            #pragma unroll
            for (int r = 0; r < 4; r++) acc[i][j][r] = 0.f;

    mma_mainloop(g_att, Bt, row0, col0, As, Bs, acc);

    int tid = threadIdx.x, wid = tid >> 5, lane = tid & 31;
    int g = lane >> 2, tig = lane & 3;
    int wm = wid & 3, wn = wid >> 2;
    #pragma unroll
    for (int mf = 0; mf < 2; mf++) {
        int r0 = row0 + wm * 32 + mf * 16 + g;
        int r1 = r0 + 8;
        #pragma unroll
        for (int nf = 0; nf < 8; nf++) {
            int col = col0 + wn * 64 + nf * 8 + 2 * tig;
            float2 bias = *(const float2*)(bo + col);
            float2 o0, o1;
            o0.x = acc[mf][nf][0] + bias.x;
            o0.y = acc[mf][nf][1] + bias.y;
            o1.x = acc[mf][nf][2] + bias.x;
            o1.y = acc[mf][nf][3] + bias.y;
            *(float2*)(Out + (size_t)r0 * DD + col) = o0;
            *(float2*)(Out + (size_t)r1 * DD + col) = o1;
        }
    }
}

// ---------------------------------------------------------------------------
// Kernel 2a: split-KV causal attention, shifted lag bias, cp.async pipeline.
// grid (40, 16) x 256.
// ---------------------------------------------------------------------------
#define KS_STR 68
#define VS_STR 72
#define PS_STR 36

__global__ __launch_bounds__(256) void attn_mma() {
    __shared__ float Ks[2][32 * KS_STR];
    __shared__ float Vs[2][32 * VS_STR];
    __shared__ float Ps[8][16 * PS_STR];

    int u = blockIdx.x;
    int qt = c_qt[u], seg = c_sg[u];
    int bh = blockIdx.y, h = bh & (HH-1);
    int tid = threadIdx.x, wid = tid >> 5, lane = tid & 31;
    int g = lane >> 2, tig = lane & 3;
    int q0 = qt * 128 + wid * 16;

    int kstart = seg * 512;
    int kend = min((seg + 1) * 512, (qt + 1) * 128);
    int nch = (kend - kstart) >> 5;

    const float* qp = g_q + (size_t)bh * TT * DH;
    const float* kp = g_k + (size_t)bh * TT * DH;
    const float* vp = g_v + (size_t)bh * TT * DH;

    // shifted lag bias in registers (zero for lag >= MAXLAG)
    float bias[MAXLAG+1];
    {
        float c5 = g_lagp[h*(MAXLAG+1) + MAXLAG];
        #pragma unroll
        for (int i = 0; i <= MAXLAG; i++) bias[i] = g_lagp[h*(MAXLAG+1)+i] - c5;
    }

    // Q fragments pre-scaled by 1/8 (exact in tf32)
    uint32_t qa[8][4];
    #pragma unroll
    for (int kf = 0; kf < 8; kf++) {
        qa[kf][0] = __float_as_uint(0.125f * qp[(size_t)(q0 + g    ) * DH + kf*8 + tig    ]);
        qa[kf][1] = __float_as_uint(0.125f * qp[(size_t)(q0 + 8 + g) * DH + kf*8 + tig    ]);
        qa[kf][2] = __float_as_uint(0.125f * qp[(size_t)(q0 + g    ) * DH + kf*8 + tig + 4]);
        qa[kf][3] = __float_as_uint(0.125f * qp[(size_t)(q0 + 8 + g) * DH + kf*8 + tig + 4]);
    }

    float O[8][4];
    #pragma unroll
    for (int i = 0; i < 8; i++)
        #pragma unroll
        for (int r = 0; r < 4; r++) O[i][r] = 0.f;
    float mA = -1e30f, mB = -1e30f, lA = 0.f, lB = 0.f;

    int qiA = q0 + g, qiB = q0 + 8 + g;
    float* Pw = Ps[wid];

    // cp.async slots: thread covers rows r_, r_+16, 16B at col c4_*4
    int r_ = tid >> 4, c4_ = tid & 15;
    uint32_t kd[2][2], vd[2][2];
    #pragma unroll
    for (int b = 0; b < 2; b++)
        #pragma unroll
        for (int i = 0; i < 2; i++) {
            kd[b][i] = smem_u32(&Ks[b][(r_ + i*16) * KS_STR + c4_*4]);
            vd[b][i] = smem_u32(&Vs[b][(r_ + i*16) * VS_STR + c4_*4]);
        }
    const char* kg = (const char*)(kp + (size_t)(kstart + r_)*DH + c4_*4);
    const char* vg = (const char*)(vp + (size_t)(kstart + r_)*DH + c4_*4);
    const long CH = (long)32 * DH * 4, HF = (long)16 * DH * 4;

    {   // prologue: chunk 0
        CP_ASYNC16(kd[0][0], kg); CP_ASYNC16(kd[0][1], kg + HF);
        CP_ASYNC16(vd[0][0], vg); CP_ASYNC16(vd[0][1], vg + HF);
        CP_COMMIT();
    }

    for (int c = 0; c < nch; c++) {
        int j0 = kstart + c * 32;
        int b = c & 1;
        CP_WAIT0();
        __syncthreads();
        if (c + 1 < nch) {
            int nb = b ^ 1;
            long off = (long)(c + 1) * CH;
            CP_ASYNC16(kd[nb][0], kg + off); CP_ASYNC16(kd[nb][1], kg + off + HF);
            CP_ASYNC16(vd[nb][0], vg + off); CP_ASYNC16(vd[nb][1], vg + off + HF);
            CP_COMMIT();
        }

        if (j0 <= q0 + 15) {
            float s[4][4];
            #pragma unroll
            for (int nf = 0; nf < 4; nf++)
                #pragma unroll
                for (int r = 0; r < 4; r++) s[nf][r] = 0.f;
            const uint32_t* Ku = (const uint32_t*)Ks[b];
            #pragma unroll
            for (int kf = 0; kf < 8; kf++) {
                int k = kf * 8;
                #pragma unroll
                for (int nf = 0; nf < 4; nf++) {
                    int nb2 = nf * 8 + g;
                    uint32_t b0 = Ku[nb2 * KS_STR + k + tig];
                    uint32_t b1 = Ku[nb2 * KS_STR + k + tig + 4];
                    mma8(s[nf], qa[kf], b0, b1);
                }
            }
            float rmaxA = -1e30f, rmaxB = -1e30f;
            if (j0 + 36 > q0) {
                // diagonal chunk: mask + shifted bias
                #pragma unroll
                for (int nf = 0; nf < 4; nf++) {
                    int jc = j0 + nf * 8 + 2 * tig;
                    #pragma unroll
                    for (int uu = 0; uu < 2; uu++) {
                        int jj = jc + uu;
                        int lagA = qiA - jj; lagA = lagA < 0 ? 0 : (lagA > MAXLAG ? MAXLAG : lagA);
                        int lagB = qiB - jj; lagB = lagB < 0 ? 0 : (lagB > MAXLAG ? MAXLAG : lagB);
                        float vA = (jj <= qiA) ? (s[nf][uu]   + bias[lagA]) : -1e30f;
                        float vB = (jj <= qiB) ? (s[nf][2+uu] + bias[lagB]) : -1e30f;
                        s[nf][uu]   = vA;  rmaxA = fmaxf(rmaxA, vA);
                        s[nf][2+uu] = vB;  rmaxB = fmaxf(rmaxB, vB);
                    }
                }
            } else {
                // far-past chunk: no mask, bias identically zero
                #pragma unroll
                for (int nf = 0; nf < 4; nf++) {
                    rmaxA = fmaxf(rmaxA, fmaxf(s[nf][0], s[nf][1]));
                    rmaxB = fmaxf(rmaxB, fmaxf(s[nf][2], s[nf][3]));
                }
            }
            rmaxA = fmaxf(rmaxA, __shfl_xor_sync(0xffffffffu, rmaxA, 1, 4));
            rmaxA = fmaxf(rmaxA, __shfl_xor_sync(0xffffffffu, rmaxA, 2, 4));
            rmaxB = fmaxf(rmaxB, __shfl_xor_sync(0xffffffffu, rmaxB, 1, 4));
            rmaxB = fmaxf(rmaxB, __shfl_xor_sync(0xffffffffu, rmaxB, 2, 4));
            float nmA = fmaxf(mA, rmaxA), nmB = fmaxf(mB, rmaxB);
            float corrA = __expf(mA - nmA), corrB = __expf(mB - nmB);
            mA = nmA; mB = nmB;
            #pragma unroll
            for (int nf = 0; nf < 8; nf++) {
                O[nf][0] *= corrA; O[nf][1] *= corrA;
                O[nf][2] *= corrB; O[nf][3] *= corrB;
            }
            float psA = 0.f, psB = 0.f;
            #pragma unroll
            for (int nf = 0; nf < 4; nf++) {
                float p0 = __expf(s[nf][0] - mA);
                float p1 = __expf(s[nf][1] - mA);
                float p2 = __expf(s[nf][2] - mB);
                float p3 = __expf(s[nf][3] - mB);
                psA += p0 + p1; psB += p2 + p3;
                int colc = nf * 8 + 2 * tig;
                Pw[g * PS_STR + colc]           = __uint_as_float(f2tf(p0));
                Pw[g * PS_STR + colc + 1]       = __uint_as_float(f2tf(p1));
                Pw[(g + 8) * PS_STR + colc]     = __uint_as_float(f2tf(p2));
                Pw[(g + 8) * PS_STR + colc + 1] = __uint_as_float(f2tf(p3));
            }
            psA += __shfl_xor_sync(0xffffffffu, psA, 1, 4);
            psA += __shfl_xor_sync(0xffffffffu, psA, 2, 4);
            psB += __shfl_xor_sync(0xffffffffu, psB, 1, 4);
            psB += __shfl_xor_sync(0xffffffffu, psB, 2, 4);
            lA = lA * corrA + psA;
            lB = lB * corrB + psB;
            __syncwarp();

            const uint32_t* Pu = (const uint32_t*)Pw;
            const uint32_t* Vu = (const uint32_t*)Vs[b];
            #pragma unroll
            for (int kf = 0; kf < 4; kf++) {
                int k = kf * 8;
                uint32_t a[4];
                a[0] = Pu[g * PS_STR + k + tig];
                a[1] = Pu[(g + 8) * PS_STR + k + tig];
                a[2] = Pu[g * PS_STR + k + tig + 4];
                a[3] = Pu[(g + 8) * PS_STR + k + tig + 4];
                #pragma unroll
                for (int nf = 0; nf < 8; nf++) {
                    uint32_t b0 = Vu[(k + tig) * VS_STR + nf * 8 + g];
                    uint32_t b1 = Vu[(k + tig + 4) * VS_STR + nf * 8 + g];
                    mma8(O[nf], a, b0, b1);
                }
            }
            __syncwarp();
        }
    }

    // write unnormalized partials
    int base = (bh * NQT + qt) * MAXSEG + seg;
    float* pO = g_pO + (size_t)base * 128 * 64;
    int rA = wid * 16 + g, rB = rA + 8;
    #pragma unroll
    for (int nf = 0; nf < 8; nf++) {
        int d = nf * 8 + 2 * tig;
        *(float2*)(pO + rA * 64 + d) = make_float2(O[nf][0], O[nf][1]);
        *(float2*)(pO + rB * 64 + d) = make_float2(O[nf][2], O[nf][3]);
    }
    if (tig == 0) {
        g_pm[base * 128 + rA] = mA; g_pl[base * 128 + rA] = lA;
        g_pm[base * 128 + rB] = mB; g_pl[base * 128 + rB] = lB;
    }
}

// ---------------------------------------------------------------------------
// Kernel 2b: combine partials -> g_att.  grid (16 qt, 16 bh) x 256.
// ---------------------------------------------------------------------------
__global__ __launch_bounds__(256) void attn_combine() {
    int qt = blockIdx.x, bh = blockIdx.y;
    int h = bh & (HH-1), b_ = bh >> 3;
    int nseg = (qt >> 2) + 1;
    int base0 = (bh * NQT + qt) * MAXSEG;
    int tid = threadIdx.x;

    #pragma unroll
    for (int it = 0; it < 8; it++) {
        int p = tid + it * 256;
        int r = p >> 4, d4 = p & 15;
        float m = -1e30f;
        for (int s = 0; s < nseg; s++)
            m = fmaxf(m, g_pm[(base0 + s) * 128 + r]);
        float w[MAXSEG];
        float L = 0.f;
        for (int s = 0; s < nseg; s++) {
            w[s] = __expf(g_pm[(base0 + s) * 128 + r] - m);
            L += w[s] * g_pl[(base0 + s) * 128 + r];
        }
        float inv = 1.f / L;
        float4 a = make_float4(0.f, 0.f, 0.f, 0.f);
        for (int s = 0; s < nseg; s++) {
            const float4 v = *(const float4*)(g_pO +
                ((size_t)(base0 + s) * 128 + r) * 64 + d4 * 4);
            a.x += w[s] * v.x; a.y += w[s] * v.y;
            a.z += w[s] * v.z; a.w += w[s] * v.w;
        }
        a.x *= inv; a.y *= inv; a.z *= inv; a.w *= inv;
        int qi = qt * 128 + r;
        *(float4*)(g_att + ((size_t)(b_ * TT + qi)) * NINNER + h * DH + d4 * 4) = a;
    }
}

// ---------------------------------------------------------------------------
extern "C" void kernel_launch(void* const* d_in, const int* in_sizes, int n_in,
                              void* d_out, int out_size) {
    const float* x  = (const float*)d_in[0];
    const float* Wq = (const float*)d_in[1];
    const float* Wk = (const float*)d_in[2];
    const float* Wv = (const float*)d_in[3];
    const float* Wo = (const float*)d_in[4];
    const float* bo = (const float*)d_in[5];
    const float* lw = (const float*)d_in[6];
    float* out = (float*)d_out;

    lag_softmax_kernel<<<1, 32>>>(lw);
    transpose_w_kernel<<<dim3(16, 16, 4), 256>>>(Wq, Wk, Wv, Wo);
    gemm_qkv_mma<<<dim3(NINNER/128, BT/128, 3), 256>>>(x);
    attn_mma<<<dim3(40, NBH), 256>>>();
    attn_combine<<<dim3(NQT, NBH), 256>>>();
    gemm_out_mma<<<dim3(DD/128, BT/128), 256>>>(bo, out);
}